// round 3
// baseline (speedup 1.0000x reference)
#include <cuda_runtime.h>
#include <math_constants.h>
#include <stdint.h>

#define N_BINS 15
#define C_DIM  100

// Global accumulators: [0..14]=counts, [15..29]=conf_sum, [30..44]=acc_sum
__device__ float g_acc[3 * N_BINS];
__device__ int   g_is64;   // 1 if labels are int64, 0 if int32

// Zero accumulators AND detect label dtype.
// Viewing the labels buffer as int32: for int64 data with values < 2^31,
// every odd word is 0 (little-endian high half). For int32 data, odd words
// are random labels in [0,100) -> virtually never all zero.
// We only read indices < n, which is in-bounds for BOTH layouts.
__global__ void ece_zero_kernel(const int* __restrict__ labels32, int n) {
    __shared__ int s_any;
    if (threadIdx.x == 0) s_any = 0;
    __syncthreads();

    if (threadIdx.x < 3 * N_BINS) g_acc[threadIdx.x] = 0.0f;

    int any = 0;
    for (int idx = 1 + 2 * threadIdx.x; idx < n; idx += 2 * blockDim.x) {
        if (labels32[idx] != 0) { any = 1; break; }
    }
    if (any) atomicOr(&s_any, 1);
    __syncthreads();
    if (threadIdx.x == 0) g_is64 = (s_any == 0) ? 1 : 0;
}

__global__ void __launch_bounds__(256) ece_accum_kernel(
    const float* __restrict__ logits,
    const void*  __restrict__ labels_raw,
    int n, int vec_ok)
{
    __shared__ float s_acc[3 * N_BINS];
    for (int i = threadIdx.x; i < 3 * N_BINS; i += blockDim.x) s_acc[i] = 0.0f;
    __syncthreads();

    const int is64 = g_is64;
    const int* __restrict__       lab32 = (const int*)labels_raw;
    const long long* __restrict__ lab64 = (const long long*)labels_raw;

    const int lane   = threadIdx.x & 31;
    const int warp   = (int)((blockIdx.x * blockDim.x + threadIdx.x) >> 5);
    const int nwarps = (int)((gridDim.x * blockDim.x) >> 5);

    for (int row = warp; row < n; row += nwarps) {
        const float* rowp = logits + (size_t)row * C_DIM;

        float m  = -CUDART_INF_F;
        int   mi = 0x7fffffff;   // inactive lanes never win ties
        if (vec_ok) {
            if (lane < 25) {
                float4 v = reinterpret_cast<const float4*>(rowp)[lane];
                int base = lane * 4;
                m = v.x; mi = base;
                if (v.y > m) { m = v.y; mi = base + 1; }
                if (v.z > m) { m = v.z; mi = base + 2; }
                if (v.w > m) { m = v.w; mi = base + 3; }
            }
        } else {
            #pragma unroll
            for (int j = 0; j < 4; j++) {
                int c = lane + j * 32;
                if (c < C_DIM) {
                    float v = rowp[c];
                    if (v > m || (v == m && c < mi)) { m = v; mi = c; }
                }
            }
        }
        // Warp reduce max with first-index tie-break (matches jnp.argmax).
        #pragma unroll
        for (int off = 16; off > 0; off >>= 1) {
            float om = __shfl_down_sync(0xffffffffu, m,  off);
            int   oi = __shfl_down_sync(0xffffffffu, mi, off);
            if (om > m || (om == m && oi < mi)) { m = om; mi = oi; }
        }

        if (lane == 0) {
            // sigmoid is monotone: conf = sigmoid(max logit); argmax unchanged
            float conf = 1.0f / (1.0f + __expf(-m));

            // searchsorted(linspace(0,1,16), conf, 'left') - 1, clipped
            int idx = N_BINS + 1;
            #pragma unroll
            for (int i = 0; i <= N_BINS; i++) {
                float b = (i == N_BINS) ? 1.0f : (float)i * (1.0f / 15.0f);
                if (b >= conf) { idx = i; break; }
            }
            int bin = idx - 1;
            bin = bin < 0 ? 0 : (bin > N_BINS - 1 ? N_BINS - 1 : bin);

            int lab = is64 ? (int)lab64[row] : lab32[row];
            float acc = (mi == lab) ? 1.0f : 0.0f;
            atomicAdd(&s_acc[bin],              1.0f);
            atomicAdd(&s_acc[N_BINS + bin],     conf);
            atomicAdd(&s_acc[2 * N_BINS + bin], acc);
        }
    }

    __syncthreads();
    for (int i = threadIdx.x; i < 3 * N_BINS; i += blockDim.x) {
        float v = s_acc[i];
        if (v != 0.0f) atomicAdd(&g_acc[i], v);
    }
}

__global__ void ece_final_kernel(float* __restrict__ out, float inv_n) {
    if (threadIdx.x == 0 && blockIdx.x == 0) {
        float ece = 0.0f;
        #pragma unroll
        for (int b = 0; b < N_BINS; b++) {
            float cnt = g_acc[b];
            if (cnt > 0.0f) {
                float avg_conf = g_acc[N_BINS + b] / cnt;
                float avg_acc  = g_acc[2 * N_BINS + b] / cnt;
                ece += (avg_conf - avg_acc) * (cnt * inv_n);
            }
        }
        out[0] = ece;
    }
}

extern "C" void kernel_launch(void* const* d_in, const int* in_sizes, int n_in,
                              void* d_out, int out_size) {
    // Resolve input order by element count: logits has C_DIM x as many
    // elements as labels.
    long long s0 = in_sizes[0], s1 = in_sizes[1];
    int logits_idx = (s0 > s1) ? 0 : 1;
    int labels_idx = 1 - logits_idx;

    const float* logits     = (const float*)d_in[logits_idx];
    const void*  labels_raw = d_in[labels_idx];
    int n = (int)((s0 < s1) ? s0 : s1);
    float* out = (float*)d_out;

    int vec_ok = ((uintptr_t)logits & 15) == 0 ? 1 : 0;

    ece_zero_kernel<<<1, 256>>>((const int*)labels_raw, n);

    const int threads = 256;
    const int blocks  = 2368;            // ~16 blocks/SM
    ece_accum_kernel<<<blocks, threads>>>(logits, labels_raw, n, vec_ok);

    ece_final_kernel<<<1, 32>>>(out, 1.0f / (float)n);
}